// round 1
// baseline (speedup 1.0000x reference)
#include <cuda_runtime.h>

// LbpBlock: out = concat([x, pad(x_cat)], ch axis)
//   y[n,o,h,w]   = sum_c x[n,c,h,w] * conv_w[o,c]          (c=3, o=64)
//   x_cat[n,o,i,j] (interior 254x254) = sum_l H(y_c - y_sl) * exp(w[o,l])
//   padded to 256x256 with zero border.
//
// x: (8,3,256,256) f32, conv_w: (64,3) f32, w: (64,8) f32
// out: (8,67,256,256) f32

#define NN   8
#define CIN  3
#define OCH  64
#define HH   256
#define WW   256
#define TH   16
#define TW   64
#define OC   4                  // output channels per chunk (float4 packed)
#define NCHUNK (OCH / OC)       // 16
#define HALO_H (TH + 2)         // 18
#define HALO_W (TW + 2)         // 66
#define HALO_N (HALO_H * HALO_W)// 1188
#define CP   75                 // swizzled float4 row pitch (max sw(65)=73)

__device__ __forceinline__ int sw(int c) { return c + (c >> 3); }

__global__ __launch_bounds__(256)
void lbp_main(const float* __restrict__ x,
              const float* __restrict__ cw,
              const float* __restrict__ w,
              float* __restrict__ out)
{
    __shared__ float4 sy[HALO_H][CP];          // y for 4 channels of current chunk
    __shared__ __align__(16) float sew[OCH][8];// exp(w)
    __shared__ __align__(16) float scw[OCH][4];// conv_w (padded row)

    const int tid = threadIdx.x;
    const int n   = blockIdx.z;
    const int h0  = blockIdx.y * TH;           // tile origin (covers full image)
    const int w0  = blockIdx.x * TW;

    // ---- one-time preloads ----
    for (int i = tid; i < OCH * 8; i += 256)
        sew[i >> 3][i & 7] = __expf(w[i]) ;
    for (int i = tid; i < OCH; i += 256) {
        scw[i][0] = cw[i * 3 + 0];
        scw[i][1] = cw[i * 3 + 1];
        scw[i][2] = cw[i * 3 + 2];
        scw[i][3] = 0.f;
    }

    // x halo cached in registers: each thread owns up to 5 halo pixels
    float xr[5][3];
    int   syoff[5];
    #pragma unroll
    for (int k = 0; k < 5; k++) {
        int p = tid + k * 256;
        float v0 = 0.f, v1 = 0.f, v2 = 0.f;
        int r = p / HALO_W;
        int c = p - r * HALO_W;
        syoff[k] = r * CP + sw(c);
        if (p < HALO_N) {
            int gh = h0 - 1 + r;
            int gw = w0 - 1 + c;
            if (gh >= 0 && gh < HH && gw >= 0 && gw < WW) {
                int base = (n * CIN * HH + gh) * WW + gw;
                v0 = x[base];
                v1 = x[base + HH * WW];
                v2 = x[base + 2 * HH * WW];
            }
        }
        xr[k][0] = v0; xr[k][1] = v1; xr[k][2] = v2;
    }
    __syncthreads();

    const int mc = tid & 15;       // micro-col (4 px wide)
    const int mr = tid >> 4;       // row within tile
    const int oh = h0 + mr;
    const int owbase = w0 + mc * 4;
    const bool hvalid = (oh >= 1 && oh <= HH - 2);

    for (int ch = 0; ch < NCHUNK; ch++) {
        const int o0 = ch * OC;

        // per-chunk weights into registers (broadcast LDS)
        float ew[OC][8];
        float cwr[OC][3];
        #pragma unroll
        for (int oc = 0; oc < OC; oc++) {
            float4 e0 = *(const float4*)&sew[o0 + oc][0];
            float4 e1 = *(const float4*)&sew[o0 + oc][4];
            ew[oc][0] = e0.x; ew[oc][1] = e0.y; ew[oc][2] = e0.z; ew[oc][3] = e0.w;
            ew[oc][4] = e1.x; ew[oc][5] = e1.y; ew[oc][6] = e1.z; ew[oc][7] = e1.w;
            float4 c4 = *(const float4*)&scw[o0 + oc][0];
            cwr[oc][0] = c4.x; cwr[oc][1] = c4.y; cwr[oc][2] = c4.z;
        }

        // ---- phase 1: y halo for this chunk (from register-cached x) ----
        #pragma unroll
        for (int k = 0; k < 5; k++) {
            int p = tid + k * 256;
            if (p < HALO_N) {
                float x0 = xr[k][0], x1 = xr[k][1], x2 = xr[k][2];
                float4 v;
                v.x = fmaf(x2, cwr[0][2], fmaf(x1, cwr[0][1], x0 * cwr[0][0]));
                v.y = fmaf(x2, cwr[1][2], fmaf(x1, cwr[1][1], x0 * cwr[1][0]));
                v.z = fmaf(x2, cwr[2][2], fmaf(x1, cwr[2][1], x0 * cwr[2][0]));
                v.w = fmaf(x2, cwr[3][2], fmaf(x1, cwr[3][1], x0 * cwr[3][0]));
                ((float4*)sy)[syoff[k]] = v;
            }
        }
        __syncthreads();

        // ---- phase 2: LBP for 1x4 pixels, 4 channels ----
        float4 a[3][6];
        #pragma unroll
        for (int r = 0; r < 3; r++)
            #pragma unroll
            for (int c = 0; c < 6; c++)
                a[r][c] = sy[mr + r][sw(mc * 4 + c)];

        float res[OC][4];   // [oc][jj]
        #pragma unroll
        for (int jj = 0; jj < 4; jj++) {
            const float4 ce = a[1][jj + 1];
            float acc0 = 0.f, acc1 = 0.f, acc2 = 0.f, acc3 = 0.f;

            #define ACCUM(S, L) { const float4 s_ = (S);            \
                if (ce.x > s_.x) acc0 += ew[0][L];                  \
                if (ce.y > s_.y) acc1 += ew[1][L];                  \
                if (ce.z > s_.z) acc2 += ew[2][L];                  \
                if (ce.w > s_.w) acc3 += ew[3][L]; }

            // shift order: TL, T, TR, L, BL, B, BR, R  (matches reference)
            ACCUM(a[0][jj    ], 0)
            ACCUM(a[0][jj + 1], 1)
            ACCUM(a[0][jj + 2], 2)
            ACCUM(a[1][jj    ], 3)
            ACCUM(a[2][jj    ], 4)
            ACCUM(a[2][jj + 1], 5)
            ACCUM(a[2][jj + 2], 6)
            ACCUM(a[1][jj + 2], 7)
            #undef ACCUM

            const int ow = owbase + jj;
            const bool v = hvalid && (ow >= 1) && (ow <= WW - 2);
            res[0][jj] = v ? acc0 : 0.f;
            res[1][jj] = v ? acc1 : 0.f;
            res[2][jj] = v ? acc2 : 0.f;
            res[3][jj] = v ? acc3 : 0.f;
        }

        // aligned, fully-coalesced float4 stores (one per channel)
        const int ob = ((n * 67 + 3 + o0) * HH + oh) * WW + owbase;
        #pragma unroll
        for (int oc = 0; oc < OC; oc++)
            *(float4*)(out + ob + oc * HH * WW) =
                make_float4(res[oc][0], res[oc][1], res[oc][2], res[oc][3]);

        __syncthreads();   // sy reused next chunk
    }
}

// copy x -> out channels [0,3)
__global__ __launch_bounds__(256)
void copy_x(const float4* __restrict__ x4, float4* __restrict__ out4)
{
    const int i = blockIdx.x * 256 + threadIdx.x;
    const int plane4 = HH * WW / 4;                 // 16384
    if (i >= NN * CIN * plane4) return;
    const int nc  = i / plane4;
    const int rem = i - nc * plane4;
    const int n = nc / CIN, c = nc - n * CIN;
    out4[(n * 67 + c) * plane4 + rem] = x4[i];
}

extern "C" void kernel_launch(void* const* d_in, const int* in_sizes, int n_in,
                              void* d_out, int out_size)
{
    const float* x  = (const float*)d_in[0];
    const float* cw = (const float*)d_in[1];
    const float* w  = (const float*)d_in[2];
    float* out = (float*)d_out;

    copy_x<<<(NN * CIN * HH * WW / 4 + 255) / 256, 256>>>(
        (const float4*)x, (float4*)out);

    dim3 grid(WW / TW, HH / TH, NN);   // (4, 16, 8)
    lbp_main<<<grid, 256>>>(x, cw, w, out);
}